// round 11
// baseline (speedup 1.0000x reference)
#include <cuda_runtime.h>
#include <cuda_bf16.h>

#define NBX 512
#define NBY 512
#define BSX_F 1.953125f           /* 1000/512, exact in fp32 */
#define INV_BSX_F 0.512f          /* 512/1000 */
#define NBINS (NBX * NBY)

#define NTILES 64
#define ROWS_PER_TILE 8           /* NBX / NTILES */
#define NPART (NTILES * NBY)

#define NBLOCKS 128
#define NTHREADS 512
#define NTOT (NBLOCKS * NTHREADS)

// Scale = 1/(BSX*BSY*CAP); CAP_H == CAP_V == 0.1 so one scale serves both maps.
__device__ __constant__ float d_scale = (float)(1.0 / (1.953125 * 1.953125 * 0.1));

// Interleaved difference plane: .x = h-weighted, .y = v-weighted. 2 MB, L2-resident.
__device__ __align__(16) float2 g_d[NBINS];
// Per-(tile, column) partial sums (accumulated atomically in the row-scan phase).
__device__ __align__(16) float2 g_part[NPART];

// Grid barrier state: low 32 bits = arrive count, high 32 bits = generation.
// Monotonic across graph replays (gen never wraps in practice) -> no reset needed.
__device__ unsigned long long g_bar = 0ULL;

__device__ __forceinline__ void grid_barrier() {
    __syncthreads();
    if (threadIdx.x == 0) {
        __threadfence();                       // release: my phase writes visible
        unsigned long long old = atomicAdd(&g_bar, 1ULL);
        unsigned gen = (unsigned)(old >> 32);
        if ((unsigned)(old & 0xFFFFFFFFu) == NBLOCKS - 1) {
            // last arriver: count -= NBLOCKS, gen += 1 (single atomic, exact carry)
            atomicAdd(&g_bar, (1ULL << 32) - (unsigned long long)NBLOCKS);
        } else {
            while ((unsigned)(__ldcg(&g_bar) >> 32) == gen) __nanosleep(32);
        }
    }
    __syncthreads();
    __threadfence();                           // acquire side
}

// f(i) = clip(min(hi_v, e[i+1]) - max(lo_v, e[i]), 0, BSX) -- reference formula verbatim.
__device__ __forceinline__ float overlap_f(float lo_v, float hi_v, int i) {
    float lo = fmaxf(lo_v, (float)i * BSX_F);
    float hi = fminf(hi_v, (float)(i + 1) * BSX_F);
    return fminf(fmaxf(hi - lo, 0.0f), BSX_F);
}

// Exact bin index: floor(v / BSX) with fixup against exact fp32 edges.
__device__ __forceinline__ int bin_of(float v) {
    int i = (int)(v * INV_BSX_F);
    if (v < (float)i * BSX_F) i--;
    else if (v >= (float)(i + 1) * BSX_F) i++;
    return i;
}

// Change-points of f along one axis: at most 4 nonzero first differences.
__device__ __forceinline__ int build_diffs(float lo_v, float hi_v, int* idx, float* df) {
    int i0 = bin_of(lo_v);
    int i1 = bin_of(hi_v);
    int cand[4]; int nc = 0;
    cand[nc++] = i0;
    cand[nc++] = i0 + 1;
    if (i1 > i0) {
        if (i1 > i0 + 1) cand[nc++] = i1;
        cand[nc++] = i1 + 1;
    }
    int n = 0;
    #pragma unroll
    for (int k = 0; k < 4; k++) {
        if (k >= nc) break;
        int i = cand[k];
        if (i < 0 || i >= NBX) continue;
        float fprev = (i > 0) ? overlap_f(lo_v, hi_v, i - 1) : 0.0f;
        float d = overlap_f(lo_v, hi_v, i) - fprev;
        if (d != 0.0f) { idx[n] = i; df[n] = d; n++; }
    }
    return n;
}

__global__ __launch_bounds__(NTHREADS, 2)
void rudy_fused_kernel(const float* __restrict__ pin_pos,
                       const float* __restrict__ net_weights,
                       const int*   __restrict__ netpin_start,
                       const int*   __restrict__ flat_netpin,
                       float* __restrict__ out,
                       int num_nets, int P) {
    const int tid  = threadIdx.x;
    const int gtid = blockIdx.x * NTHREADS + tid;

    // ── Phase 0: zero both scratch planes (vectorized float4 stores). ──
    {
        float4 z = make_float4(0.0f, 0.0f, 0.0f, 0.0f);
        float4* d4 = reinterpret_cast<float4*>(g_d);
        float4* p4 = reinterpret_cast<float4*>(g_part);
        for (int i = gtid; i < NBINS / 2; i += NTOT) d4[i] = z;
        for (int i = gtid; i < NPART / 2; i += NTOT) p4[i] = z;
    }
    grid_barrier();

    // ── Phase 1: per-net bbox + 16-point second-difference scatter. ──
    for (int n = gtid; n < num_nets; n += NTOT) {
        int s = netpin_start[n];
        int e = netpin_start[n + 1];

        float xmin = 3.0e38f, xmax = -3.0e38f, ymin = 3.0e38f, ymax = -3.0e38f;
        for (int p = s; p < e; p++) {
            int pi = flat_netpin[p];
            float x = __ldg(&pin_pos[pi]);
            float y = __ldg(&pin_pos[P + pi]);
            xmin = fminf(xmin, x); xmax = fmaxf(xmax, x);
            ymin = fminf(ymin, y); ymax = fmaxf(ymax, y);
        }

        float w  = net_weights[n];
        float dx = xmax - xmin;
        float dy = ymax - ymin;
        float wh = (dy > 0.0f) ? (w / dy) : 0.0f;
        float wv = (dx > 0.0f) ? (w / dx) : 0.0f;

        int   ix[4], iy[4];
        float dfx[4], dfy[4];
        int nx = build_diffs(xmin, xmax, ix, dfx);
        int ny = build_diffs(ymin, ymax, iy, dfy);

        for (int a = 0; a < nx; a++) {
            int rowbase = ix[a] * NBY;
            float fh = dfx[a] * wh;
            float fv = dfx[a] * wv;
            for (int b = 0; b < ny; b++) {
                float g = dfy[b];
                atomicAdd(&g_d[rowbase + iy[b]], make_float2(fh * g, fv * g));
            }
        }
    }
    grid_barrier();

    // ── Phase 2: inclusive row scan (along j) + fold tile partials. ──
    // One block per row, 4 rows per block. __ldcg: data written by other blocks.
    {
        __shared__ float2 wsum[16];
        int lane = tid & 31;
        int wid  = tid >> 5;
        for (int row = blockIdx.x; row < NBX; row += NBLOCKS) {
            float2 v;
            {
                const float2* src = &g_d[row * NBY + tid];
                v.x = __ldcg(&src->x);
                v.y = __ldcg(&src->y);
            }
            #pragma unroll
            for (int off = 1; off < 32; off <<= 1) {
                float tx = __shfl_up_sync(0xFFFFFFFFu, v.x, off);
                float ty = __shfl_up_sync(0xFFFFFFFFu, v.y, off);
                if (lane >= off) { v.x += tx; v.y += ty; }
            }
            if (lane == 31) wsum[wid] = v;
            __syncthreads();
            if (wid == 0) {
                float2 t = (lane < 16) ? wsum[lane] : make_float2(0.0f, 0.0f);
                #pragma unroll
                for (int off = 1; off < 16; off <<= 1) {
                    float ux = __shfl_up_sync(0xFFFFFFFFu, t.x, off);
                    float uy = __shfl_up_sync(0xFFFFFFFFu, t.y, off);
                    if (lane >= off) { t.x += ux; t.y += uy; }
                }
                if (lane < 16) wsum[lane] = t;
            }
            __syncthreads();
            if (wid > 0) { v.x += wsum[wid - 1].x; v.y += wsum[wid - 1].y; }
            g_d[row * NBY + tid] = v;

            atomicAdd(&g_part[(row >> 3) * NBY + tid], v);
            __syncthreads();   /* wsum reuse across row iterations */
        }
    }
    grid_barrier();

    // ── Phase 3: per-(tile, column) exclusive prefix (4-way unrolled for MLP)
    // + in-tile running sums + finalize. One unit per thread, 32768 units. ──
    for (int u = gtid; u < NTILES * NBY; u += NTOT) {
        int t = u >> 9;          /* u / NBY */
        int j = u & (NBY - 1);

        float sh0 = 0.0f, sv0 = 0.0f, sh1 = 0.0f, sv1 = 0.0f;
        float sh2 = 0.0f, sv2 = 0.0f, sh3 = 0.0f, sv3 = 0.0f;
        int tp = 0;
        for (; tp + 4 <= t; tp += 4) {
            const float2* p0 = &g_part[(tp + 0) * NBY + j];
            const float2* p1 = &g_part[(tp + 1) * NBY + j];
            const float2* p2 = &g_part[(tp + 2) * NBY + j];
            const float2* p3 = &g_part[(tp + 3) * NBY + j];
            sh0 += __ldcg(&p0->x); sv0 += __ldcg(&p0->y);
            sh1 += __ldcg(&p1->x); sv1 += __ldcg(&p1->y);
            sh2 += __ldcg(&p2->x); sv2 += __ldcg(&p2->y);
            sh3 += __ldcg(&p3->x); sv3 += __ldcg(&p3->y);
        }
        for (; tp < t; tp++) {
            const float2* p = &g_part[tp * NBY + j];
            sh0 += __ldcg(&p->x); sv0 += __ldcg(&p->y);
        }
        float sh = (sh0 + sh1) + (sh2 + sh3);
        float sv = (sv0 + sv1) + (sv2 + sv3);

        float sc = d_scale;
        int base = t * ROWS_PER_TILE * NBY + j;
        #pragma unroll
        for (int r = 0; r < ROWS_PER_TILE; r++) {
            const float2* d = &g_d[base + r * NBY];
            sh += __ldcg(&d->x);
            sv += __ldcg(&d->y);
            out[base + r * NBY] = fmaxf(fabsf(sh * sc), fabsf(sv * sc));
        }
    }
}

extern "C" void kernel_launch(void* const* d_in, const int* in_sizes, int n_in,
                              void* d_out, int out_size) {
    const float* pin_pos      = (const float*)d_in[0];
    const float* net_weights  = (const float*)d_in[1];
    const int*   netpin_start = (const int*)  d_in[2];
    const int*   flat_netpin  = (const int*)  d_in[3];
    float* out = (float*)d_out;

    int num_nets = in_sizes[2] - 1;
    int P        = in_sizes[0] / 2;

    rudy_fused_kernel<<<NBLOCKS, NTHREADS>>>(pin_pos, net_weights,
                                             netpin_start, flat_netpin,
                                             out, num_nets, P);
}

// round 12
// speedup vs baseline: 1.3693x; 1.3693x over previous
#include <cuda_runtime.h>
#include <cuda_bf16.h>

#define NBX 512
#define NBY 512
#define BSX_F 1.953125f           /* 1000/512, exact in fp32 */
#define INV_BSX_F 0.512f          /* 512/1000 */
#define NBINS (NBX * NBY)

#define NTILES 64
#define ROWS_PER_TILE 8           /* NBX / NTILES */
#define NPART (NTILES * NBY)

// Scale = 1/(BSX*BSY*CAP); CAP_H == CAP_V == 0.1 so one scale serves both maps.
__device__ __constant__ float d_scale = (float)(1.0 / (1.953125 * 1.953125 * 0.1));

// Interleaved difference plane: .x = h-weighted, .y = v-weighted. 2 MB, L2-resident.
__device__ __align__(16) float2 g_d[NBINS];
// Per-(tile, column) partial sums for the column scan (accumulated atomically).
__device__ __align__(16) float2 g_part[NPART];

// Zero both scratch planes with vectorized stores.
__global__ void zero_planes() {
    int i = blockIdx.x * blockDim.x + threadIdx.x;
    float4 z = make_float4(0.0f, 0.0f, 0.0f, 0.0f);
    if (i < NBINS / 2)  reinterpret_cast<float4*>(g_d)[i] = z;
    if (i < NPART / 2)  reinterpret_cast<float4*>(g_part)[i] = z;
}

// f(i) = clip(min(hi_v, e[i+1]) - max(lo_v, e[i]), 0, BSX) -- reference formula verbatim.
__device__ __forceinline__ float overlap_f(float lo_v, float hi_v, int i) {
    float lo = fmaxf(lo_v, (float)i * BSX_F);
    float hi = fminf(hi_v, (float)(i + 1) * BSX_F);
    return fminf(fmaxf(hi - lo, 0.0f), BSX_F);
}

// Exact bin index: floor(v / BSX) with fixup against exact fp32 edges.
__device__ __forceinline__ int bin_of(float v) {
    int i = (int)(v * INV_BSX_F);
    if (v < (float)i * BSX_F) i--;
    else if (v >= (float)(i + 1) * BSX_F) i++;
    return i;
}

// Change-points of f along one axis: at most 4 nonzero first differences.
__device__ __forceinline__ int build_diffs(float lo_v, float hi_v, int* idx, float* df) {
    int i0 = bin_of(lo_v);
    int i1 = bin_of(hi_v);
    int cand[4]; int nc = 0;
    cand[nc++] = i0;
    cand[nc++] = i0 + 1;
    if (i1 > i0) {
        if (i1 > i0 + 1) cand[nc++] = i1;
        cand[nc++] = i1 + 1;
    }
    int n = 0;
    #pragma unroll
    for (int k = 0; k < 4; k++) {
        if (k >= nc) break;
        int i = cand[k];
        if (i < 0 || i >= NBX) continue;
        float fprev = (i > 0) ? overlap_f(lo_v, hi_v, i - 1) : 0.0f;
        float d = overlap_f(lo_v, hi_v, i) - fprev;
        if (d != 0.0f) { idx[n] = i; df[n] = d; n++; }
    }
    return n;
}

__global__ void scatter_kernel(const float* __restrict__ pin_pos,
                               const float* __restrict__ net_weights,
                               const int*   __restrict__ netpin_start,
                               const int*   __restrict__ flat_netpin,
                               int num_nets, int P) {
    int n = blockIdx.x * blockDim.x + threadIdx.x;
    if (n >= num_nets) return;
    int s = netpin_start[n];
    int e = netpin_start[n + 1];

    float xmin = 3.0e38f, xmax = -3.0e38f, ymin = 3.0e38f, ymax = -3.0e38f;
    for (int p = s; p < e; p++) {
        int pi = flat_netpin[p];
        float x = __ldg(&pin_pos[pi]);
        float y = __ldg(&pin_pos[P + pi]);
        xmin = fminf(xmin, x); xmax = fmaxf(xmax, x);
        ymin = fminf(ymin, y); ymax = fmaxf(ymax, y);
    }

    float w  = net_weights[n];
    float dx = xmax - xmin;
    float dy = ymax - ymin;
    float wh = (dy > 0.0f) ? (w / dy) : 0.0f;   // horizontal map weight
    float wv = (dx > 0.0f) ? (w / dx) : 0.0f;   // vertical map weight

    int   ix[4], iy[4];
    float dfx[4], dfy[4];
    int nx = build_diffs(xmin, xmax, ix, dfx);
    int ny = build_diffs(ymin, ymax, iy, dfy);

    for (int a = 0; a < nx; a++) {
        int rowbase = ix[a] * NBY;
        float fh = dfx[a] * wh;
        float fv = dfx[a] * wv;
        for (int b = 0; b < ny; b++) {
            float g = dfy[b];
            atomicAdd(&g_d[rowbase + iy[b]], make_float2(fh * g, fv * g));
        }
    }
}

// Inclusive scan along j (fast axis) for each row, both planes at once.
// Each thread then atomically folds its final scanned value into its tile's
// column partial. grid = NBX, block = 512.
__global__ void row_scan_kernel() {
    int row = blockIdx.x;
    int tid = threadIdx.x;
    int lane = tid & 31;
    int wid  = tid >> 5;

    float2 v = g_d[row * NBY + tid];
    #pragma unroll
    for (int off = 1; off < 32; off <<= 1) {
        float tx = __shfl_up_sync(0xFFFFFFFFu, v.x, off);
        float ty = __shfl_up_sync(0xFFFFFFFFu, v.y, off);
        if (lane >= off) { v.x += tx; v.y += ty; }
    }
    __shared__ float2 wsum[16];
    if (lane == 31) wsum[wid] = v;
    __syncthreads();
    if (wid == 0) {
        float2 t = (lane < 16) ? wsum[lane] : make_float2(0.0f, 0.0f);
        #pragma unroll
        for (int off = 1; off < 16; off <<= 1) {
            float ux = __shfl_up_sync(0xFFFFFFFFu, t.x, off);
            float uy = __shfl_up_sync(0xFFFFFFFFu, t.y, off);
            if (lane >= off) { t.x += ux; t.y += uy; }
        }
        if (lane < 16) wsum[lane] = t;
    }
    __syncthreads();
    if (wid > 0) { v.x += wsum[wid - 1].x; v.y += wsum[wid - 1].y; }
    g_d[row * NBY + tid] = v;

    int t = row >> 3;   /* row / ROWS_PER_TILE */
    atomicAdd(&g_part[t * NBY + tid], v);
}

// Column finalize: redundant exclusive prefix over preceding tiles' partials
// (4 independent accumulators -> dependent-load chain / 4) + in-tile running
// sums + output. grid = (NBY/256, NTILES), block = 256.
__global__ void col_finalize_kernel(float* __restrict__ out) {
    int j = blockIdx.x * blockDim.x + threadIdx.x;
    int t = blockIdx.y;

    float sh0 = 0.0f, sv0 = 0.0f, sh1 = 0.0f, sv1 = 0.0f;
    float sh2 = 0.0f, sv2 = 0.0f, sh3 = 0.0f, sv3 = 0.0f;
    int tp = 0;
    for (; tp + 4 <= t; tp += 4) {
        float2 p0 = g_part[(tp + 0) * NBY + j];
        float2 p1 = g_part[(tp + 1) * NBY + j];
        float2 p2 = g_part[(tp + 2) * NBY + j];
        float2 p3 = g_part[(tp + 3) * NBY + j];
        sh0 += p0.x; sv0 += p0.y;
        sh1 += p1.x; sv1 += p1.y;
        sh2 += p2.x; sv2 += p2.y;
        sh3 += p3.x; sv3 += p3.y;
    }
    for (; tp < t; tp++) {
        float2 p = g_part[tp * NBY + j];
        sh0 += p.x; sv0 += p.y;
    }
    float sh = (sh0 + sh1) + (sh2 + sh3);
    float sv = (sv0 + sv1) + (sv2 + sv3);

    float sc = d_scale;
    int base = t * ROWS_PER_TILE * NBY + j;
    #pragma unroll
    for (int r = 0; r < ROWS_PER_TILE; r++) {
        float2 d = g_d[base + r * NBY];
        sh += d.x;
        sv += d.y;
        out[base + r * NBY] = fmaxf(fabsf(sh * sc), fabsf(sv * sc));
    }
}

extern "C" void kernel_launch(void* const* d_in, const int* in_sizes, int n_in,
                              void* d_out, int out_size) {
    const float* pin_pos      = (const float*)d_in[0];
    const float* net_weights  = (const float*)d_in[1];
    const int*   netpin_start = (const int*)  d_in[2];
    const int*   flat_netpin  = (const int*)  d_in[3];
    float* out = (float*)d_out;

    int num_nets = in_sizes[2] - 1;
    int P        = in_sizes[0] / 2;

    zero_planes<<<(NBINS / 2 + 255) / 256, 256>>>();
    scatter_kernel<<<(num_nets + 255) / 256, 256>>>(pin_pos, net_weights,
                                                    netpin_start, flat_netpin,
                                                    num_nets, P);
    row_scan_kernel<<<NBX, NBY>>>();
    col_finalize_kernel<<<dim3(NBY / 256, NTILES), 256>>>(out);
}

// round 13
// speedup vs baseline: 1.5743x; 1.1497x over previous
#include <cuda_runtime.h>
#include <cuda_bf16.h>

#define NBX 512
#define NBY 512
#define BSX_F 1.953125f           /* 1000/512, exact in fp32 */
#define INV_BSX_F 0.512f          /* 512/1000 */
#define NBINS (NBX * NBY)

// Scale = 1/(BSX*BSY*CAP); CAP_H == CAP_V == 0.1 so one scale serves both maps.
__device__ __constant__ float d_scale = (float)(1.0 / (1.953125 * 1.953125 * 0.1));

// Interleaved difference plane: .x = h-weighted, .y = v-weighted. 2 MB, L2-resident.
__device__ __align__(16) float2 g_d[NBINS];
// Row-scanned plane, stored transposed: g_dT[j * NBX + i]. Fully overwritten
// by row_scan each run -> no zeroing needed.
__device__ __align__(16) float2 g_dT[NBINS];

// Zero the diff plane with vectorized stores.
__global__ void zero_planes() {
    int i = blockIdx.x * blockDim.x + threadIdx.x;
    if (i < NBINS / 2)
        reinterpret_cast<float4*>(g_d)[i] = make_float4(0.0f, 0.0f, 0.0f, 0.0f);
}

// f(i) = clip(min(hi_v, e[i+1]) - max(lo_v, e[i]), 0, BSX) -- reference formula verbatim.
__device__ __forceinline__ float overlap_f(float lo_v, float hi_v, int i) {
    float lo = fmaxf(lo_v, (float)i * BSX_F);
    float hi = fminf(hi_v, (float)(i + 1) * BSX_F);
    return fminf(fmaxf(hi - lo, 0.0f), BSX_F);
}

// Exact bin index: floor(v / BSX) with fixup against exact fp32 edges.
__device__ __forceinline__ int bin_of(float v) {
    int i = (int)(v * INV_BSX_F);
    if (v < (float)i * BSX_F) i--;
    else if (v >= (float)(i + 1) * BSX_F) i++;
    return i;
}

// Change-points of f along one axis: at most 4 nonzero first differences.
__device__ __forceinline__ int build_diffs(float lo_v, float hi_v, int* idx, float* df) {
    int i0 = bin_of(lo_v);
    int i1 = bin_of(hi_v);
    int cand[4]; int nc = 0;
    cand[nc++] = i0;
    cand[nc++] = i0 + 1;
    if (i1 > i0) {
        if (i1 > i0 + 1) cand[nc++] = i1;
        cand[nc++] = i1 + 1;
    }
    int n = 0;
    #pragma unroll
    for (int k = 0; k < 4; k++) {
        if (k >= nc) break;
        int i = cand[k];
        if (i < 0 || i >= NBX) continue;
        float fprev = (i > 0) ? overlap_f(lo_v, hi_v, i - 1) : 0.0f;
        float d = overlap_f(lo_v, hi_v, i) - fprev;
        if (d != 0.0f) { idx[n] = i; df[n] = d; n++; }
    }
    return n;
}

__global__ void scatter_kernel(const float* __restrict__ pin_pos,
                               const float* __restrict__ net_weights,
                               const int*   __restrict__ netpin_start,
                               const int*   __restrict__ flat_netpin,
                               int num_nets, int P) {
    int n = blockIdx.x * blockDim.x + threadIdx.x;
    if (n >= num_nets) return;
    int s = netpin_start[n];
    int e = netpin_start[n + 1];

    float xmin = 3.0e38f, xmax = -3.0e38f, ymin = 3.0e38f, ymax = -3.0e38f;
    for (int p = s; p < e; p++) {
        int pi = flat_netpin[p];
        float x = __ldg(&pin_pos[pi]);
        float y = __ldg(&pin_pos[P + pi]);
        xmin = fminf(xmin, x); xmax = fmaxf(xmax, x);
        ymin = fminf(ymin, y); ymax = fmaxf(ymax, y);
    }

    float w  = net_weights[n];
    float dx = xmax - xmin;
    float dy = ymax - ymin;
    float wh = (dy > 0.0f) ? (w / dy) : 0.0f;   // horizontal map weight
    float wv = (dx > 0.0f) ? (w / dx) : 0.0f;   // vertical map weight

    int   ix[4], iy[4];
    float dfx[4], dfy[4];
    int nx = build_diffs(xmin, xmax, ix, dfx);
    int ny = build_diffs(ymin, ymax, iy, dfy);

    for (int a = 0; a < nx; a++) {
        int rowbase = ix[a] * NBY;
        float fh = dfx[a] * wh;
        float fv = dfx[a] * wv;
        for (int b = 0; b < ny; b++) {
            float g = dfy[b];
            atomicAdd(&g_d[rowbase + iy[b]], make_float2(fh * g, fv * g));
        }
    }
}

// Block-wide inclusive scan of a float2 held per-thread (512 threads).
__device__ __forceinline__ float2 block_scan_512(float2 v, float2* wsum) {
    int tid = threadIdx.x;
    int lane = tid & 31;
    int wid  = tid >> 5;
    #pragma unroll
    for (int off = 1; off < 32; off <<= 1) {
        float tx = __shfl_up_sync(0xFFFFFFFFu, v.x, off);
        float ty = __shfl_up_sync(0xFFFFFFFFu, v.y, off);
        if (lane >= off) { v.x += tx; v.y += ty; }
    }
    if (lane == 31) wsum[wid] = v;
    __syncthreads();
    if (wid == 0) {
        float2 t = (lane < 16) ? wsum[lane] : make_float2(0.0f, 0.0f);
        #pragma unroll
        for (int off = 1; off < 16; off <<= 1) {
            float ux = __shfl_up_sync(0xFFFFFFFFu, t.x, off);
            float uy = __shfl_up_sync(0xFFFFFFFFu, t.y, off);
            if (lane >= off) { t.x += ux; t.y += uy; }
        }
        if (lane < 16) wsum[lane] = t;
    }
    __syncthreads();
    if (wid > 0) { v.x += wsum[wid - 1].x; v.y += wsum[wid - 1].y; }
    return v;
}

// Inclusive scan along j for each row; result written TRANSPOSED into g_dT.
// grid = NBX, block = 512.
__global__ void row_scan_kernel() {
    __shared__ float2 wsum[16];
    int row = blockIdx.x;
    int tid = threadIdx.x;

    float2 v = g_d[row * NBY + tid];
    v = block_scan_512(v, wsum);
    g_dT[tid * NBX + row] = v;   // scattered 8B stores; fire-and-forget
}

// Inclusive scan along i for each column (coalesced via g_dT) + finalize.
// grid = NBY, block = 512. Thread tid = row index i of column j = blockIdx.x.
__global__ void col_scan_kernel(float* __restrict__ out) {
    __shared__ float2 wsum[16];
    int j   = blockIdx.x;
    int tid = threadIdx.x;

    float2 v = g_dT[j * NBX + tid];
    v = block_scan_512(v, wsum);

    float sc = d_scale;
    out[tid * NBY + j] = fmaxf(fabsf(v.x * sc), fabsf(v.y * sc));
}

extern "C" void kernel_launch(void* const* d_in, const int* in_sizes, int n_in,
                              void* d_out, int out_size) {
    const float* pin_pos      = (const float*)d_in[0];
    const float* net_weights  = (const float*)d_in[1];
    const int*   netpin_start = (const int*)  d_in[2];
    const int*   flat_netpin  = (const int*)  d_in[3];
    float* out = (float*)d_out;

    int num_nets = in_sizes[2] - 1;
    int P        = in_sizes[0] / 2;

    zero_planes<<<(NBINS / 2 + 255) / 256, 256>>>();
    scatter_kernel<<<(num_nets + 255) / 256, 256>>>(pin_pos, net_weights,
                                                    netpin_start, flat_netpin,
                                                    num_nets, P);
    row_scan_kernel<<<NBX, NBY>>>();
    col_scan_kernel<<<NBY, NBX>>>(out);
}